// round 5
// baseline (speedup 1.0000x reference)
#include <cuda_runtime.h>
#include <math.h>

#define B_    64
#define N_    20000
#define D_    128
#define F1_   512
#define F2_   256
#define KSEL  20

// ---------------- scratch (device globals; no allocation allowed) ----------
__device__ float g_V[N_ * D_];        // V rows
__device__ float g_logT[N_ * B_];     // logits transposed [n][b]
__device__ float g_Q[B_ * D_];
__device__ float g_qpT[D_ * B_];      // q_part transposed [d][b]
__device__ int   g_maxenc[B_];        // per-b max logit (order-preserving int enc)
__device__ int   g_sel[B_ * KSEL];    // argmax indices

__device__ __forceinline__ int enc_f(float f) {
    int i = __float_as_int(f);
    return i >= 0 ? i : i ^ 0x7fffffff;
}
__device__ __forceinline__ float dec_f(int i) {
    return __int_as_float(i >= 0 ? i : i ^ 0x7fffffff);
}

// ---------------- packed f32x2 helpers (sm_103a FFMA2) ----------------------
__device__ __forceinline__ unsigned long long pk2(float lo, float hi) {
    unsigned long long r;
    asm("mov.b64 %0, {%1, %2};" : "=l"(r) : "f"(lo), "f"(hi));
    return r;
}
__device__ __forceinline__ void upk2(unsigned long long v, float& lo, float& hi) {
    asm("mov.b64 {%0, %1}, %2;" : "=f"(lo), "=f"(hi) : "l"(v));
}
__device__ __forceinline__ void fma2(unsigned long long& d,
                                     unsigned long long a, unsigned long long b) {
    asm("fma.rn.f32x2 %0, %1, %2, %0;" : "+l"(d) : "l"(a), "l"(b));
}

__global__ void k_init() {
    if (threadIdx.x < B_) g_maxenc[threadIdx.x] = (int)0x80000000;
}

// ---------------- Kernel A: Q = pe@Wq+bq ; q_part = Q@W1[:D] ----------------
__global__ __launch_bounds__(128) void k_A(
    const float* __restrict__ pe, const float* __restrict__ Wq,
    const float* __restrict__ bq, const float* __restrict__ W1)
{
    __shared__ float pe_s[F1_];
    __shared__ float q_s[D_];
    int b = blockIdx.x, d = threadIdx.x;
    for (int i = d; i < F1_; i += 128) pe_s[i] = pe[b * F1_ + i];
    __syncthreads();
    float acc = 0.f;
#pragma unroll 8
    for (int f = 0; f < F1_; ++f) acc = fmaf(pe_s[f], Wq[f * D_ + d], acc);
    acc += bq[d];
    g_Q[b * D_ + d] = acc;
    q_s[d] = acc;
    __syncthreads();
    float a2 = 0.f;
#pragma unroll 8
    for (int e = 0; e < D_; ++e) a2 = fmaf(q_s[e], W1[e * D_ + d], a2);
    g_qpT[d * B_ + b] = a2;                    // store transposed
}

// ---------------- Kernel B: per-gene fused Km/V/k_part/logits ---------------
// 32 genes per block, 256 threads. Phases 2+3 use packed FFMA2.
// dynamic smem floats: [0:8192) ge tile (reused as qpT), [8192:12288) Km,
//                      [12288:16384) k_part+b1, [16384:16512) w2.
__global__ __launch_bounds__(256) void k_B(
    const float* __restrict__ ge,
    const float* __restrict__ Wk, const float* __restrict__ bk,
    const float* __restrict__ Wv, const float* __restrict__ bv,
    const float* __restrict__ W1, const float* __restrict__ b1,
    const float* __restrict__ w2, const float* __restrict__ b2)
{
    extern __shared__ float sm[];
    float* ge_s = sm;                  // 8192 (later: qpT [d][b])
    float* km_s = sm + 8192;           // 4096
    float* kp_s = sm + 12288;          // 4096
    float* w2_s = sm + 16384;          // 128

    int t  = threadIdx.x;
    int n0 = blockIdx.x * 32;

    // phase 1: load 32x256 gene tile
    {
        const float4* src = (const float4*)(ge + (size_t)n0 * F2_);
        float4* dst = (float4*)ge_s;
#pragma unroll
        for (int i = 0; i < 8; ++i) dst[t + i * 256] = src[t + i * 256];
    }
    __syncthreads();

    int d = t & 127, gh = t >> 7;      // column d, 16 genes each half

    // phase 2: Km and V (packed: gene pairs (2j, 2j+1))
    unsigned long long accK2[8], accV2[8];
#pragma unroll
    for (int j = 0; j < 8; ++j) { accK2[j] = 0ull; accV2[j] = 0ull; }
    const float* gb = ge_s + gh * 16 * F2_;
    for (int f = 0; f < F2_; f += 4) {
        unsigned long long wkp[4], wvp[4];
#pragma unroll
        for (int q = 0; q < 4; ++q) {
            float wk = Wk[(f + q) * D_ + d];
            float wv = Wv[(f + q) * D_ + d];
            wkp[q] = pk2(wk, wk);
            wvp[q] = pk2(wv, wv);
        }
#pragma unroll
        for (int j = 0; j < 8; ++j) {
            float4 a = *(const float4*)(gb + (2 * j) * F2_ + f);
            float4 c = *(const float4*)(gb + (2 * j + 1) * F2_ + f);
            unsigned long long p0 = pk2(a.x, c.x), p1 = pk2(a.y, c.y);
            unsigned long long p2 = pk2(a.z, c.z), p3 = pk2(a.w, c.w);
            fma2(accK2[j], p0, wkp[0]); fma2(accK2[j], p1, wkp[1]);
            fma2(accK2[j], p2, wkp[2]); fma2(accK2[j], p3, wkp[3]);
            fma2(accV2[j], p0, wvp[0]); fma2(accV2[j], p1, wvp[1]);
            fma2(accV2[j], p2, wvp[2]); fma2(accV2[j], p3, wvp[3]);
        }
    }
    {
        float bkd = bk[d], bvd = bv[d];
#pragma unroll
        for (int j = 0; j < 8; ++j) {
            float k0, k1, v0, v1;
            upk2(accK2[j], k0, k1); upk2(accV2[j], v0, v1);
            int g0 = gh * 16 + 2 * j, g1 = g0 + 1;
            km_s[g0 * D_ + d] = k0 + bkd;
            km_s[g1 * D_ + d] = k1 + bkd;
            g_V[(size_t)(n0 + g0) * D_ + d] = v0 + bvd;
            g_V[(size_t)(n0 + g1) * D_ + d] = v1 + bvd;
        }
    }
    __syncthreads();                   // phase2 done reading ge_s

    // overwrite ge_s with qpT [d][b]; load w2
    for (int j = t; j < B_ * D_; j += 256) ge_s[j] = g_qpT[j];
    if (t < D_) w2_s[t] = w2[t];

    // phase 3: k_part (+b1), packed gene pairs
    unsigned long long accP2[8];
#pragma unroll
    for (int j = 0; j < 8; ++j) accP2[j] = 0ull;
    for (int e = 0; e < D_; e += 4) {
        unsigned long long w1p[4];
#pragma unroll
        for (int q = 0; q < 4; ++q) {
            float w = W1[(D_ + e + q) * D_ + d];
            w1p[q] = pk2(w, w);
        }
#pragma unroll
        for (int j = 0; j < 8; ++j) {
            float4 a = *(const float4*)(km_s + (gh * 16 + 2 * j) * D_ + e);
            float4 c = *(const float4*)(km_s + (gh * 16 + 2 * j + 1) * D_ + e);
            unsigned long long p0 = pk2(a.x, c.x), p1 = pk2(a.y, c.y);
            unsigned long long p2 = pk2(a.z, c.z), p3 = pk2(a.w, c.w);
            fma2(accP2[j], p0, w1p[0]); fma2(accP2[j], p1, w1p[1]);
            fma2(accP2[j], p2, w1p[2]); fma2(accP2[j], p3, w1p[3]);
        }
    }
    __syncthreads();                   // km_s reads done before kp_s overwrite-adjacent use
    {
        float b1d = b1[d];
#pragma unroll
        for (int j = 0; j < 8; ++j) {
            float p0, p1;
            upk2(accP2[j], p0, p1);
            int g0 = gh * 16 + 2 * j, g1 = g0 + 1;
            kp_s[g0 * D_ + d] = p0 + b1d;
            kp_s[g1 * D_ + d] = p1 + b1d;
        }
    }
    __syncthreads();

    // phase 4: sim -> logits  (thread owns batch b, 8 genes)
    int b  = t & 63, gq = t >> 6;
    float acc[8];
#pragma unroll
    for (int i = 0; i < 8; ++i) acc[i] = 0.f;
    const float* kpg = kp_s + gq * 8 * D_;
    const float* qpT = ge_s;           // [d][b]
    for (int dd = 0; dd < D_; ++dd) {
        float qp = qpT[dd * B_ + b];
        float wv = w2_s[dd];
#pragma unroll
        for (int i = 0; i < 8; ++i) {
            float x = qp + kpg[i * D_ + dd];
            float l = fmaxf(x, 0.1f * x);      // leaky_relu(x, 0.1)
            acc[i]  = fmaf(l, wv, acc[i]);
        }
    }
    float b2v = b2[0];
    float lmax = -3.4e38f;
#pragma unroll
    for (int i = 0; i < 8; ++i) {
        float lg = (acc[i] + b2v) * 2.0f;      // /TEMP, TEMP=0.5 exact
        g_logT[(size_t)(n0 + gq * 8 + i) * B_ + b] = lg;
        lmax = fmaxf(lmax, lg);
    }
    atomicMax(&g_maxenc[b], enc_f(lmax));
}

// ------- Kernel C: JAX partitionable threefry gumbel + warp-uniform prune ---
__device__ __forceinline__ void threefry(unsigned c0, unsigned c1,
                                         unsigned& o0, unsigned& o1)
{
    const unsigned k0 = 0u, k1 = 42u, k2 = 0x1BD11BDAu ^ 42u;
    unsigned x0 = c0 + k0, x1 = c1 + k1;
#define TFR(r) { x0 += x1; x1 = __funnelshift_l(x1, x1, (r)); x1 ^= x0; }
    TFR(13) TFR(15) TFR(26) TFR(6)
    x0 += k1; x1 += k2 + 1u;
    TFR(17) TFR(29) TFR(16) TFR(24)
    x0 += k2; x1 += k0 + 2u;
    TFR(13) TFR(15) TFR(26) TFR(6)
    x0 += k0; x1 += k1 + 3u;
    TFR(17) TFR(29) TFR(16) TFR(24)
    x0 += k1; x1 += k2 + 4u;
    TFR(13) TFR(15) TFR(26) TFR(6)
    x0 += k2; x1 += k0 + 5u;
#undef TFR
    o0 = x0; o1 = x1;
}

__device__ __forceinline__ float to_uni(unsigned bits) {
    // matches jax.random.uniform(minval=tiny, maxval=1) float32
    float f = __uint_as_float((bits >> 9) | 0x3f800000u) - 1.0f;
    return f > 0.f ? f : 1.17549435e-38f;
}

__global__ __launch_bounds__(256) void k_C() {
    int r = blockIdx.x;                // r = b*KSEL + k, 1280 blocks
    int b = r / KSEL;
    int t = threadIdx.x;
    float Lmax = dec_f(g_maxenc[b]);
    unsigned base = (unsigned)r * (unsigned)N_;

    // warp-uniform running state
    float    M   = -3.4e38f;
    int      im  = 0;
    unsigned mth = 0u;                 // accept iff (bits>>9) >= mth; 0 = accept all

    for (int n = t; n < N_; n += 256) {
        unsigned o0, o1;
        threefry(0u, base + (unsigned)n, o0, o1);
        unsigned bits = o0 ^ o1;
        unsigned mb = bits >> 9;
        unsigned cand = __ballot_sync(0xffffffffu, mb >= mth);
        if (cand) {                    // warp-uniform, rare (~8 events/warp)
            float x  = -3.4e38f;
            int   xi = 0x7fffffff;
            if (mb >= mth) {
                float u   = to_uni(bits);
                float gum = -logf(-logf(u));
                x  = g_logT[(size_t)n * B_ + b] + gum;
                xi = n;
            }
#pragma unroll
            for (int o = 16; o; o >>= 1) {
                float ox = __shfl_xor_sync(0xffffffffu, x, o);
                int   oi = __shfl_xor_sync(0xffffffffu, xi, o);
                if (ox > x || (ox == x && oi < xi)) { x = ox; xi = oi; }
            }
            if (x > M) {
                M = x; im = xi;
                // conservative u-threshold: never reject g(u) > M - Lmax - 1e-3
                float tt = M - Lmax - 1e-3f;
                float v  = (tt > -80.f) ? expf(-expf(-tt)) * (1.0f - 1e-6f) : 0.f;
                mth = (unsigned)(v * 8388608.0f);   // trunc -> conservative
            }
        }
    }

    // cross-warp reduction (warp-uniform M/im; lane 0 of each warp reports)
    __shared__ float sv[8];
    __shared__ int   si[8];
    int wrp = t >> 5, ln = t & 31;
    if (ln == 0) { sv[wrp] = M; si[wrp] = im; }
    __syncthreads();
    if (t == 0) {
        float bm = sv[0]; int bi = si[0];
        for (int w = 1; w < 8; ++w) {
            if (sv[w] > bm || (sv[w] == bm && si[w] < bi)) { bm = sv[w]; bi = si[w]; }
        }
        g_sel[r] = bi;
    }
}

// ---------------- Kernel D: gather V, K-softmax, context --------------------
__global__ __launch_bounds__(128) void k_D(float* __restrict__ out) {
    int b = blockIdx.x, t = threadIdx.x;
    int wrp = t >> 5, ln = t & 31;
    __shared__ int   sidx[KSEL];
    __shared__ float ssc[KSEL];
    __shared__ float sw[KSEL];
    if (t < KSEL) sidx[t] = g_sel[b * KSEL + t];
    __syncthreads();
    const float* qrow = g_Q + b * D_;
    for (int k = wrp; k < KSEL; k += 4) {
        const float* vrow = g_V + (size_t)sidx[k] * D_;
        float s = 0.f;
#pragma unroll
        for (int j = 0; j < 4; ++j) { int dd = ln + 32 * j; s = fmaf(qrow[dd], vrow[dd], s); }
#pragma unroll
        for (int o = 16; o; o >>= 1) s += __shfl_xor_sync(0xffffffffu, s, o);
        if (ln == 0) ssc[k] = s * 0.08838834764831845f;   // 1/sqrt(128)
    }
    __syncthreads();
    if (t == 0) {
        float m = -3.4e38f;
        for (int k = 0; k < KSEL; ++k) m = fmaxf(m, ssc[k]);
        float sum = 0.f;
        for (int k = 0; k < KSEL; ++k) { float e = expf(ssc[k] - m); sw[k] = e; sum += e; }
        float inv = 1.0f / sum;
        for (int k = 0; k < KSEL; ++k) sw[k] *= inv;
    }
    __syncthreads();
    {
        float acc = 0.f;
#pragma unroll 4
        for (int k = 0; k < KSEL; ++k)
            acc = fmaf(sw[k], g_V[(size_t)sidx[k] * D_ + t], acc);
        out[b * D_ + t] = acc;
    }
}

// ---------------- launch -----------------------------------------------------
extern "C" void kernel_launch(void* const* d_in, const int* in_sizes, int n_in,
                              void* d_out, int out_size) {
    const float* pe = (const float*)d_in[0];
    const float* ge = (const float*)d_in[1];
    const float* Wq = (const float*)d_in[2];
    const float* bq = (const float*)d_in[3];
    const float* Wk = (const float*)d_in[4];
    const float* bk = (const float*)d_in[5];
    const float* Wv = (const float*)d_in[6];
    const float* bv = (const float*)d_in[7];
    const float* W1 = (const float*)d_in[8];
    const float* b1 = (const float*)d_in[9];
    const float* w2 = (const float*)d_in[10];
    const float* b2 = (const float*)d_in[11];

    const int SMEM_B = 16512 * sizeof(float);   // 66048 bytes
    cudaFuncSetAttribute(k_B, cudaFuncAttributeMaxDynamicSharedMemorySize, SMEM_B);

    k_init<<<1, 64>>>();
    k_A<<<B_, 128>>>(pe, Wq, bq, W1);
    k_B<<<N_ / 32, 256, SMEM_B>>>(ge, Wk, bk, Wv, bv, W1, b1, w2, b2);
    k_C<<<B_ * KSEL, 256>>>();
    k_D<<<B_, 128>>>((float*)d_out);
}